// round 7
// baseline (speedup 1.0000x reference)
#include <cuda_runtime.h>
#include <cuda_fp16.h>
#include <cstdint>

// ============================================================================
// Problem constants
// ============================================================================
static constexpr int KDIM = 4096;   // IN_DIM
static constexpr int NDIM = 4096;   // OUT_DIM
static constexpr int MDIM = 8192;   // 4 * 2048 tokens

// GEMM tiling (mma.sync path -- base sm_103 ISA, no tcgen05)
static constexpr int BM = 128;
static constexpr int BN = 128;
static constexpr int BK = 64;                 // fp16 elems per K-chunk (128 B rows)
static constexpr int KTILES = KDIM / BK;      // 64
static constexpr int STAGES = 3;

static constexpr int TILE_BYTES = BM * 128;               // 16 KB (A stage == B stage)
static constexpr int SMEM_BYTES = STAGES * 2 * TILE_BYTES; // 96 KB

// ============================================================================
// Scratch (device globals -- no allocation allowed)
// ============================================================================
__device__ __align__(16) __half g_x_h[(size_t)MDIM * KDIM];   // x in fp16
__device__ __align__(16) __half g_w_h[(size_t)NDIM * KDIM];   // dequant+LoRA W'

__constant__ float c_nf4[16] = {
    -1.0f, -0.6961928009986877f, -0.5250730514526367f, -0.39491748809814453f,
    -0.28444138169288635f, -0.18477343022823334f, -0.09105003625154495f, 0.0f,
    0.07958029955625534f, 0.16093020141124725f, 0.24611230194568634f,
    0.33791524171829224f, 0.44070982933044434f, 0.5626170039176941f,
    0.7229568362236023f, 1.0f};

// ============================================================================
// Helpers
// ============================================================================
__device__ __forceinline__ uint32_t smem_u32(const void* p) {
    uint32_t a;
    asm("{ .reg .u64 t; cvta.to.shared.u64 t, %1; cvt.u32.u64 %0, t; }" : "=r"(a) : "l"(p));
    return a;
}

// SW128 swizzle for 128-byte rows (Swizzle<3,4,3>): XOR row%8 into 16B-chunk idx.
__device__ __forceinline__ uint32_t swz(uint32_t byte_off) {
    return byte_off ^ ((byte_off >> 3) & 0x70);
}

#define CP_ASYNC_16(dst, src) \
    asm volatile("cp.async.cg.shared.global [%0], [%1], 16;" :: "r"(dst), "l"(src))
#define CP_ASYNC_COMMIT() asm volatile("cp.async.commit_group;" ::: "memory")
#define CP_ASYNC_WAIT_1() asm volatile("cp.async.wait_group 1;" ::: "memory")

// ============================================================================
// Kernel 1: x f32 -> fp16 (8 elements / thread; streaming loads)
// ============================================================================
__global__ void __launch_bounds__(256) convert_x_kernel(const float4* __restrict__ xin,
                                                        int4* __restrict__ xout) {
    int t = blockIdx.x * blockDim.x + threadIdx.x;
    float4 a = __ldcs(&xin[2 * t]);
    float4 b = __ldcs(&xin[2 * t + 1]);
    __half2 h[4];
    h[0] = __floats2half2_rn(a.x, a.y);
    h[1] = __floats2half2_rn(a.z, a.w);
    h[2] = __floats2half2_rn(b.x, b.y);
    h[3] = __floats2half2_rn(b.z, b.w);
    xout[t] = *reinterpret_cast<int4*>(h);
}

// ============================================================================
// Kernel 2: NF4 dequant + double-dequant scalers + LoRA merge -> fp16 W'
//   W'[o,i] = NF4[idx[o,i]] * (q_scalers[blk]/q_factor[blk/256] + mean)
//             + 2.0 * sum_r B[o,r] * A[r,i]
// 8 consecutive i per thread (one 16 B store).
// ============================================================================
__global__ void __launch_bounds__(256) dequant_merge_kernel(
    const int* __restrict__ nf4_idx, const int* __restrict__ q_scalers,
    const float* __restrict__ q_factor, const float* __restrict__ scaler_mean,
    const float* __restrict__ lora_a, const float* __restrict__ lora_b,
    __half* __restrict__ wout)
{
    int t  = blockIdx.x * blockDim.x + threadIdx.x;   // 2,097,152 threads
    int o  = t >> 9;                                  // row (512 threads per row)
    int i0 = (t & 511) << 3;                          // col start
    int blk = (o << 6) + (i0 >> 6);                   // nf4 block (64 cols / block)

    float sc = (float)q_scalers[blk] / q_factor[blk >> 8] + scaler_mean[0];

    // LoRA: acc[j] = 2 * sum_r B[o,r] * A[r, i0+j]
    float bv[16];
    const float4* lb4 = reinterpret_cast<const float4*>(lora_b + o * 16);
#pragma unroll
    for (int q = 0; q < 4; q++) {
        float4 b = lb4[q];
        bv[q * 4 + 0] = 2.0f * b.x; bv[q * 4 + 1] = 2.0f * b.y;
        bv[q * 4 + 2] = 2.0f * b.z; bv[q * 4 + 3] = 2.0f * b.w;
    }
    float acc[8];
#pragma unroll
    for (int j = 0; j < 8; j++) acc[j] = 0.0f;
#pragma unroll
    for (int r = 0; r < 16; r++) {
        const float4* ar = reinterpret_cast<const float4*>(lora_a + r * KDIM + i0);
        float4 u = ar[0], v = ar[1];
        acc[0] = fmaf(bv[r], u.x, acc[0]); acc[1] = fmaf(bv[r], u.y, acc[1]);
        acc[2] = fmaf(bv[r], u.z, acc[2]); acc[3] = fmaf(bv[r], u.w, acc[3]);
        acc[4] = fmaf(bv[r], v.x, acc[4]); acc[5] = fmaf(bv[r], v.y, acc[5]);
        acc[6] = fmaf(bv[r], v.z, acc[6]); acc[7] = fmaf(bv[r], v.w, acc[7]);
    }

    const int4* ip = reinterpret_cast<const int4*>(nf4_idx + (size_t)o * KDIM + i0);
    int4 q0 = __ldcs(ip);          // nf4 indices are read-once -> streaming
    int4 q1 = __ldcs(ip + 1);
    __half h[8];
    h[0] = __float2half_rn(fmaf(c_nf4[q0.x], sc, acc[0]));
    h[1] = __float2half_rn(fmaf(c_nf4[q0.y], sc, acc[1]));
    h[2] = __float2half_rn(fmaf(c_nf4[q0.z], sc, acc[2]));
    h[3] = __float2half_rn(fmaf(c_nf4[q0.w], sc, acc[3]));
    h[4] = __float2half_rn(fmaf(c_nf4[q1.x], sc, acc[4]));
    h[5] = __float2half_rn(fmaf(c_nf4[q1.y], sc, acc[5]));
    h[6] = __float2half_rn(fmaf(c_nf4[q1.z], sc, acc[6]));
    h[7] = __float2half_rn(fmaf(c_nf4[q1.w], sc, acc[7]));
    *reinterpret_cast<int4*>(wout + (size_t)o * KDIM + i0) = *reinterpret_cast<int4*>(h);
}

// ============================================================================
// Kernel 3: pipelined fp16 GEMM via mma.sync.m16n8k16 (row.col), fp32 accum.
//   C[M,N] = A[M,K] * B[N,K]^T    (A = x_h, B = W'_h; both K-major row-major)
//   CTA 128x128x64, 8 warps (4Mx2N), warp tile 32x64, 3-stage cp.async.
// ============================================================================
__global__ void __launch_bounds__(256, 2) gemm_kernel(
    const __half* __restrict__ A, const __half* __restrict__ B,
    float* __restrict__ out)
{
    extern __shared__ char smem[];
    const uint32_t sA = smem_u32(smem);
    const uint32_t sB = sA + STAGES * TILE_BYTES;

    const int tid = threadIdx.x, wid = tid >> 5, lane = tid & 31;
    const int m0 = blockIdx.y * BM, n0 = blockIdx.x * BN;
    const int warp_m = wid >> 1;        // 0..3 -> 32 rows each
    const int warp_n = wid & 1;         // 0..1 -> 64 cols each

    const __half* gA = A + (size_t)m0 * KDIM;
    const __half* gB = B + (size_t)n0 * KDIM;

    // ---- stage loader: 128 rows x 128 B each for A and B; 16 B per cp.async ----
    auto load_stage = [&](int s, int kt) {
        const uint32_t dA = sA + s * TILE_BYTES;
        const uint32_t dB = sB + s * TILE_BYTES;
        const __half* srcA = gA + kt * BK;
        const __half* srcB = gB + kt * BK;
#pragma unroll
        for (int i = 0; i < 4; i++) {
            int idx = tid + i * 256;          // 0..1023 chunks of 16 B
            int row = idx >> 3, c = idx & 7;
            uint32_t off = swz((uint32_t)(row * 128 + c * 16));
            CP_ASYNC_16(dA + off, srcA + (size_t)row * KDIM + c * 8);
            CP_ASYNC_16(dB + off, srcB + (size_t)row * KDIM + c * 8);
        }
        CP_ASYNC_COMMIT();
    };

    float acc[2][8][4];
#pragma unroll
    for (int mt = 0; mt < 2; mt++)
#pragma unroll
        for (int nt = 0; nt < 8; nt++)
#pragma unroll
            for (int q = 0; q < 4; q++) acc[mt][nt][q] = 0.0f;

    // prologue: prefetch stages 0..STAGES-2
    for (int s = 0; s < STAGES - 1; s++) load_stage(s, s);

    for (int kt = 0; kt < KTILES; kt++) {
        CP_ASYNC_WAIT_1();                 // stage kt landed
        __syncthreads();

        // Issue next-stage loads FIRST: destination stage (kt-1)%S was fully
        // consumed before the barrier above, so the copies overlap this
        // iteration's MMA work instead of queueing behind it.
        const int nk = kt + STAGES - 1;
        if (nk < KTILES) load_stage(nk % STAGES, nk);

        const int s = kt % STAGES;
        const uint32_t bA = sA + s * TILE_BYTES;
        const uint32_t bB = sB + s * TILE_BYTES;

#pragma unroll
        for (int ks = 0; ks < 4; ks++) {   // 4 k16 steps per BK=64
            // A fragments: 2 x (m16 k16) via ldmatrix.x4
            uint32_t a[2][4];
#pragma unroll
            for (int mt = 0; mt < 2; mt++) {
                int row = warp_m * 32 + mt * 16 + (lane & 15);
                uint32_t off = swz((uint32_t)(row * 128 + (ks * 2 + (lane >> 4)) * 16));
                asm volatile("ldmatrix.sync.aligned.m8n8.x4.shared.b16 {%0,%1,%2,%3}, [%4];"
                             : "=r"(a[mt][0]), "=r"(a[mt][1]), "=r"(a[mt][2]), "=r"(a[mt][3])
                             : "r"(bA + off));
            }
            // B fragments: 8 x (k16 n8); one ldmatrix.x4 covers n16 (2 tiles, both k halves)
            uint32_t b[8][2];
#pragma unroll
            for (int nt16 = 0; nt16 < 4; nt16++) {
                int n = warp_n * 64 + nt16 * 16 + ((lane >> 4) << 3) + (lane & 7);
                uint32_t off = swz((uint32_t)(n * 128 + (ks * 2 + ((lane >> 3) & 1)) * 16));
                uint32_t r0, r1, r2, r3;
                asm volatile("ldmatrix.sync.aligned.m8n8.x4.shared.b16 {%0,%1,%2,%3}, [%4];"
                             : "=r"(r0), "=r"(r1), "=r"(r2), "=r"(r3) : "r"(bB + off));
                b[2 * nt16][0] = r0;     b[2 * nt16][1] = r1;
                b[2 * nt16 + 1][0] = r2; b[2 * nt16 + 1][1] = r3;
            }
#pragma unroll
            for (int mt = 0; mt < 2; mt++)
#pragma unroll
                for (int nt = 0; nt < 8; nt++) {
                    float* c = acc[mt][nt];
                    asm volatile(
                        "mma.sync.aligned.m16n8k16.row.col.f32.f16.f16.f32 "
                        "{%0,%1,%2,%3}, {%4,%5,%6,%7}, {%8,%9}, {%0,%1,%2,%3};"
                        : "+f"(c[0]), "+f"(c[1]), "+f"(c[2]), "+f"(c[3])
                        : "r"(a[mt][0]), "r"(a[mt][1]), "r"(a[mt][2]), "r"(a[mt][3]),
                          "r"(b[nt][0]), "r"(b[nt][1]));
                }
        }
    }

    // ---- epilogue: streaming f32 stores (keep x_h / W' resident in L2
    //      across graph replays; output is never re-read by a kernel) ----
#pragma unroll
    for (int mt = 0; mt < 2; mt++) {
#pragma unroll
        for (int nt = 0; nt < 8; nt++) {
            int r  = m0 + warp_m * 32 + mt * 16 + (lane >> 2);
            int cn = n0 + warp_n * 64 + nt * 8 + (lane & 3) * 2;
            float2 v0 = make_float2(acc[mt][nt][0], acc[mt][nt][1]);
            float2 v1 = make_float2(acc[mt][nt][2], acc[mt][nt][3]);
            __stcs(reinterpret_cast<float2*>(out + (size_t)r * NDIM + cn), v0);
            __stcs(reinterpret_cast<float2*>(out + (size_t)(r + 8) * NDIM + cn), v1);
        }
    }
}

// ============================================================================
// Host: kernel_launch (graph-capturable: kernel launches only; no statics)
// ============================================================================
extern "C" void kernel_launch(void* const* d_in, const int* in_sizes, int n_in,
                              void* d_out, int out_size)
{
    const float* x         = (const float*)d_in[0];   // [4,2048,4096] f32
    const int*   nf4_idx   = (const int*)d_in[1];     // [262144,64] i32
    const int*   q_scalers = (const int*)d_in[2];     // [262144] i32
    const float* q_factor  = (const float*)d_in[3];   // [1024] f32
    const float* smean     = (const float*)d_in[4];   // [1] f32
    const float* lora_a    = (const float*)d_in[5];   // [16,4096] f32
    const float* lora_b    = (const float*)d_in[6];   // [4096,16] f32
    float*       out       = (float*)d_out;           // [4,2048,4096] f32
    (void)in_sizes; (void)n_in; (void)out_size;

    void* xh = nullptr;
    void* wh = nullptr;
    cudaGetSymbolAddress(&xh, g_x_h);
    cudaGetSymbolAddress(&wh, g_w_h);

    // 1) x -> fp16
    convert_x_kernel<<<(int)((MDIM * (size_t)KDIM / 8) / 256), 256>>>(
        (const float4*)x, (int4*)xh);
    // 2) NF4 dequant + LoRA merge -> fp16 W'
    dequant_merge_kernel<<<(int)((NDIM * (size_t)KDIM / 8) / 256), 256>>>(
        nf4_idx, q_scalers, q_factor, smean, lora_a, lora_b, (__half*)wh);

    // 3) GEMM: 32 N-tiles x 64 M-tiles = 2048 CTAs, 2 CTAs/SM (96 KB smem each)
    cudaFuncSetAttribute(gemm_kernel, cudaFuncAttributeMaxDynamicSharedMemorySize,
                         SMEM_BYTES);
    gemm_kernel<<<dim3(NDIM / BN, MDIM / BM), 256, SMEM_BYTES>>>(
        (const __half*)xh, (const __half*)wh, out);
}